// round 2
// baseline (speedup 1.0000x reference)
#include <cuda_runtime.h>

// ---------------------------------------------------------------------------
// RoutingStorage (GR4J routing): two short FIR convolutions (parallel) feeding
// a nonlinear scalar recurrence on the routing store r (chunk-parallel scan
// with warmup, exploiting the ~0.95/step contraction of the store dynamics).
// ---------------------------------------------------------------------------

#define T_MAX 262144
static __device__ float2 g_conv[T_MAX];   // {conv1, conv2} per timestep

__device__ __forceinline__ float fsqrt_approx(float x) {
    float y; asm("sqrt.approx.f32 %0, %1;" : "=f"(y) : "f"(x)); return y;
}
__device__ __forceinline__ float frsqrt_approx(float x) {
    float y; asm("rsqrt.approx.f32 %0, %1;" : "=f"(y) : "f"(x)); return y;
}

// Unit-hydrograph ordinates for X4 = 2.5 (computed in double, stored f32):
//  ord1 (3 taps), ord2 (6 taps, last is exactly 0)
__constant__ float c_o1[3] = {0.10119288512538814f, 0.47124051711455807f,
                              0.42756659776005380f};
__constant__ float c_o2[6] = {0.05059644256269407f, 0.23562025855727903f,
                              0.42756659776005380f, 0.23562025855727903f,
                              0.05059644256269407f, 0.0f};

// Kernel 1: conv1[t] = sum_j ord1[j]*pr1[t-j], conv2[t] = sum_j ord2[j]*pr2[t-j]
__global__ void conv_kernel(const float* __restrict__ x, int T) {
    int t = blockIdx.x * blockDim.x + threadIdx.x;
    if (t >= T) return;
    float c1 = 0.0f, c2 = 0.0f;
#pragma unroll
    for (int j = 0; j < 6; ++j) {
        int idx = t - j;
        if (idx >= 0) {
            float4 row = *reinterpret_cast<const float4*>(x + 4 * idx);
            // p_r = perc + (p_n - p_s);  pr1 = 0.9*p_r, pr2 = 0.1*p_r
            float pr = row.w + (row.x - row.z);
            if (j < 3) c1 += c_o1[j] * (0.9f * pr);
            c2 += c_o2[j] * (0.1f * pr);
        }
    }
    g_conv[t] = make_float2(c1, c2);
}

// Chunked scan with warmup.
constexpr int CHUNK_L = 64;    // output steps per thread
constexpr int WARMUP  = 1024;  // warmup steps (contraction ~0.95/step => ~e^-30 residual)
constexpr int UNROLL  = 4;     // double-buffered conv prefetch depth

__global__ void scan_kernel(const float* __restrict__ x2p,
                            const float* __restrict__ x3p,
                            float* __restrict__ out, int T) {
    int chunk = blockIdx.x * blockDim.x + threadIdx.x;
    int t0 = chunk * CHUNK_L;
    if (t0 >= T) return;
    int tend = t0 + CHUNK_L;          // T divisible by CHUNK_L for this problem
    if (tend > T) tend = T;
    int ws = t0 - WARMUP;
    if (ws < 0) ws = 0;               // early chunks replay exactly from t=0

    const float x2   = x2p[0];
    const float x3   = x3p[0];
    const float inv  = 1.0f / x3;
    float inv4 = inv * inv;  inv4 = inv4 * inv4;

    float* __restrict__ qout = out;       // qsim  [0, T)
    float* __restrict__ rout = out + T;   // r_store [T, 2T)

    float r = 0.0f;                   // R_INIT * x3 = 0

    // Prime the double buffer.
    float2 A[UNROLL], B[UNROLL];
#pragma unroll
    for (int k = 0; k < UNROLL; ++k) {
        int idx = ws + k; if (idx > T - 1) idx = T - 1;
        A[k] = g_conv[idx];
    }

    for (int t = ws; t < tend; t += UNROLL) {
        // Prefetch next batch (independent of the recurrence -> hides L1/L2 lat).
        int tn = t + UNROLL;
#pragma unroll
        for (int k = 0; k < UNROLL; ++k) {
            int idx = tn + k; if (idx > T - 1) idx = T - 1;
            B[k] = g_conv[idx];
        }
#pragma unroll
        for (int k = 0; k < UNROLL; ++k) {
            float c1 = A[k].x, c2 = A[k].y;
            // gw = x2 * (r/x3)^3.5  computed as u^3 * sqrt(u)
            float u   = r * inv;
            float squ = fsqrt_approx(u);
            float u3  = (u * u) * u;
            float gw  = (x2 * u3) * squ;
            // s = max(0, r + conv1 + gw)
            float s = fmaxf((r + c1) + gw, 0.0f);
            // w = 1 + (s/x3)^4 ;  r_new = s * w^(-1/4)
            float s2 = s * s;
            float w  = fmaf(s2, s2 * inv4, 1.0f);
            float p  = fsqrt_approx(frsqrt_approx(w));
            float rn = s * p;
            int tt = t + k;
            if (tt >= t0) {
                float qr = s - rn;                    // q_r
                float qd = fmaxf(c2 + gw, 0.0f);      // q_d
                qout[tt] = qr + qd;
                rout[tt] = rn;
            }
            r = rn;
        }
#pragma unroll
        for (int k = 0; k < UNROLL; ++k) A[k] = B[k];
    }
}

extern "C" void kernel_launch(void* const* d_in, const int* in_sizes, int n_in,
                              void* d_out, int out_size) {
    const float* x  = (const float*)d_in[0];
    const float* x2 = (const float*)d_in[1];
    const float* x3 = (const float*)d_in[2];
    int T = in_sizes[0] / 4;
    if (T > T_MAX) T = T_MAX;

    conv_kernel<<<(T + 255) / 256, 256>>>(x, T);

    int C = (T + CHUNK_L - 1) / CHUNK_L;
    scan_kernel<<<(C + 31) / 32, 32>>>(x2, x3, (float*)d_out, T);
}

// round 3
// speedup vs baseline: 4.2859x; 4.2859x over previous
#include <cuda_runtime.h>

// ---------------------------------------------------------------------------
// RoutingStorage (GR4J routing). Two short FIR convolutions (parallel) feed a
// nonlinear scalar recurrence on the routing store r. The recurrence is
// chunk-parallelized with a warmup (contraction ~0.955/step near attractor).
// Per-step critical path minimized:
//   - (1+u)^(-1/4) via degree-4 polynomial (no chained MUFUs)
//   - gw_{t+1} = x2*(rn/x3)^3.5 factored as [x2*(s/x3)^3.5] * (1+u)^(-7/8),
//     both computable in parallel with the rn chain.
// ---------------------------------------------------------------------------

#define T_MAX 262144
#define PAD   8
static __device__ float2 g_conv[T_MAX + PAD];   // {conv1, conv2} per timestep

__device__ __forceinline__ float fsqrt_approx(float x) {
    float y; asm("sqrt.approx.f32 %0, %1;" : "=f"(y) : "f"(x)); return y;
}

// Unit-hydrograph ordinates for X4 = 2.5:
__constant__ float c_o1[3] = {0.10119288512538814f, 0.47124051711455807f,
                              0.42756659776005380f};
__constant__ float c_o2[6] = {0.05059644256269407f, 0.23562025855727903f,
                              0.42756659776005380f, 0.23562025855727903f,
                              0.05059644256269407f, 0.0f};

__global__ void conv_kernel(const float* __restrict__ x, int T) {
    int t = blockIdx.x * blockDim.x + threadIdx.x;
    if (t >= T + PAD) return;
    if (t >= T) { g_conv[t] = make_float2(0.0f, 0.0f); return; }
    float c1 = 0.0f, c2 = 0.0f;
#pragma unroll
    for (int j = 0; j < 6; ++j) {
        int idx = t - j;
        if (idx >= 0) {
            float4 row = *reinterpret_cast<const float4*>(x + 4 * idx);
            float pr = row.w + (row.x - row.z);   // perc + (p_n - p_s)
            if (j < 3) c1 += c_o1[j] * (0.9f * pr);
            c2 += c_o2[j] * (0.1f * pr);
        }
    }
    g_conv[t] = make_float2(c1, c2);
}

constexpr int CHUNK_L = 32;   // output steps per thread
constexpr int WARMUP  = 352;  // warmup steps (residual ~7e-6 relative)
constexpr int UNROLL  = 4;

// (1+u)^(-1/4) Horner coefficients (deg 4)
#define P1 (-0.25f)
#define P2 ( 0.15625f)
#define P3 (-0.1171875f)
#define P4 ( 0.0952148438f)
// (1+u)^(-7/8) Horner coefficients (deg 4)
#define Q1 (-0.875f)
#define Q2 ( 0.8203125f)
#define Q3 (-0.7861328125f)
#define Q4 ( 0.7615661621f)

// One recurrence step. Carries (r, gw). Outputs (q, rn) for this step.
__device__ __forceinline__ void step_fn(float& r, float& gw, float c1, float c2,
                                        float x2, float inv, float inv4,
                                        float& q, float& rstore) {
    float s  = fmaxf((r + c1) + gw, 0.0f);
    float qd = fmaxf(c2 + gw, 0.0f);
    float s2 = s * s;
    float u  = (s2 * inv4) * s2;                 // (s/x3)^4
    // p = (1+u)^(-1/4)
    float p  = fmaf(u, P4, P3); p = fmaf(u, p, P2);
    p = fmaf(u, p, P1); p = fmaf(u, p, 1.0f);
    // qq = (1+u)^(-7/8)   (parallel branch)
    float qq = fmaf(u, Q4, Q3); qq = fmaf(u, qq, Q2);
    qq = fmaf(u, qq, Q1); qq = fmaf(u, qq, 1.0f);
    float rn = s * p;
    // gw_next = x2*(rn/x3)^3.5 = [x2*(s/x3)^3.5] * (1+u)^(-7/8)  (parallel)
    float v  = s * inv;
    float sv = fsqrt_approx(v);
    float v3 = (v * v) * v;
    float gs = (x2 * v3) * sv;
    q      = (s - rn) + qd;
    rstore = rn;
    r      = rn;
    gw     = gs * qq;
}

__global__ void scan_kernel(const float* __restrict__ x2p,
                            const float* __restrict__ x3p,
                            float* __restrict__ out, int T) {
    int chunk = blockIdx.x * blockDim.x + threadIdx.x;
    int t0 = chunk * CHUNK_L;
    if (t0 >= T) return;
    int tend = t0 + CHUNK_L; if (tend > T) tend = T;
    int ws = t0 - WARMUP; if (ws < 0) ws = 0;

    const float x2  = __ldg(x2p);
    const float x3  = __ldg(x3p);
    const float inv = 1.0f / x3;
    float inv2 = inv * inv, inv4 = inv2 * inv2;

    float* __restrict__ qout = out;       // qsim    [0, T)
    float* __restrict__ rout = out + T;   // r_store [T, 2T)

    float r = 0.0f, gw = 0.0f;            // R_INIT*x3 = 0  -> gw exactly 0

    float2 A[UNROLL], B[UNROLL];
#pragma unroll
    for (int k = 0; k < UNROLL; ++k) A[k] = g_conv[ws + k];

    float qdummy, rdummy;

    // Warmup: no stores. (t0 - ws) is always a multiple of UNROLL.
    for (int t = ws; t < t0; t += UNROLL) {
#pragma unroll
        for (int k = 0; k < UNROLL; ++k) B[k] = g_conv[t + UNROLL + k];
#pragma unroll
        for (int k = 0; k < UNROLL; ++k)
            step_fn(r, gw, A[k].x, A[k].y, x2, inv, inv4, qdummy, rdummy);
#pragma unroll
        for (int k = 0; k < UNROLL; ++k) A[k] = B[k];
    }

    // Output phase.
    for (int t = t0; t < tend; t += UNROLL) {
#pragma unroll
        for (int k = 0; k < UNROLL; ++k) B[k] = g_conv[t + UNROLL + k];
#pragma unroll
        for (int k = 0; k < UNROLL; ++k) {
            float q, rn;
            step_fn(r, gw, A[k].x, A[k].y, x2, inv, inv4, q, rn);
            int tt = t + k;
            if (tt < tend) { qout[tt] = q; rout[tt] = rn; }
        }
#pragma unroll
        for (int k = 0; k < UNROLL; ++k) A[k] = B[k];
    }
}

extern "C" void kernel_launch(void* const* d_in, const int* in_sizes, int n_in,
                              void* d_out, int out_size) {
    const float* x  = (const float*)d_in[0];
    const float* x2 = (const float*)d_in[1];
    const float* x3 = (const float*)d_in[2];
    int T = in_sizes[0] / 4;
    if (T > T_MAX) T = T_MAX;

    conv_kernel<<<(T + PAD + 255) / 256, 256>>>(x, T);

    int C = (T + CHUNK_L - 1) / CHUNK_L;
    scan_kernel<<<(C + 63) / 64, 64>>>(x2, x3, (float*)d_out, T);
}